// round 7
// baseline (speedup 1.0000x reference)
#include <cuda_runtime.h>
#include <cuda_bf16.h>

#define BATCH 64
#define NUM_SPEC 8
#define VOCAB 128000
#define ROWS (BATCH * NUM_SPEC)     // 512
#define HALVES (ROWS * 2)           // 1024 CTAs
#define HALF_V4 16000               // float4 per half-row
#define THREADS 320                 // 10 warps; 16000/320 = 50 f4/thread
#define UNROLL 8
#define FULL_BATCHES 6              // 6*8 = 48
#define TAIL 2                      // +2 = 50

// Device scratch (no allocation allowed).
__device__ float g_val[HALVES];
__device__ int   g_idx[HALVES];
__device__ int   g_done[BATCH];     // zero-initialized; reset by last arriver each launch

// ---------------------------------------------------------------------------
// Fused kernel: half-row argmax (1024 CTAs) + last-arriver epilogue per batch.
// Argmax semantics match jnp.argmax (first occurrence on ties): strict > keeps
// the lowest index within a thread; all reduces tie-break toward smaller index;
// half-0 vs half-1 combine uses >= (half-0 indices are always smaller).
// Output (float32):
//   [0 .. 576)   output_token_ids    [64][9]
//   [576 .. 640) num_rejected_tokens [64]
//   [640 .. 704) last_token_ids      [64]
// ---------------------------------------------------------------------------
__global__ void __launch_bounds__(THREADS) fused_rejection_kernel(
    const float* __restrict__ logits,
    const int*   __restrict__ draft,    // [64][8]
    const int*   __restrict__ bonus,    // [64][1]
    float*       __restrict__ out)
{
    const int cta  = blockIdx.x;      // 0..1023
    const int row  = cta >> 1;        // 0..511
    const int half = cta & 1;

    const float4* __restrict__ p =
        reinterpret_cast<const float4*>(logits + (size_t)row * VOCAB);

    float best = -3.402823466e+38f;
    int   bidx = 0;

    // Front-batched independent loads for MLP; absolute f4 index in row.
    int base = half * HALF_V4 + threadIdx.x;
    for (int m = 0; m < FULL_BATCHES; m++) {
        float4 v[UNROLL];
        #pragma unroll
        for (int k = 0; k < UNROLL; k++) v[k] = p[base + k * THREADS];
        #pragma unroll
        for (int k = 0; k < UNROLL; k++) {
            int e = (base + k * THREADS) * 4;
            if (v[k].x > best) { best = v[k].x; bidx = e; }
            if (v[k].y > best) { best = v[k].y; bidx = e + 1; }
            if (v[k].z > best) { best = v[k].z; bidx = e + 2; }
            if (v[k].w > best) { best = v[k].w; bidx = e + 3; }
        }
        base += UNROLL * THREADS;
    }
    {   // tail: 2 more f4 per thread
        float4 v[TAIL];
        #pragma unroll
        for (int k = 0; k < TAIL; k++) v[k] = p[base + k * THREADS];
        #pragma unroll
        for (int k = 0; k < TAIL; k++) {
            int e = (base + k * THREADS) * 4;
            if (v[k].x > best) { best = v[k].x; bidx = e; }
            if (v[k].y > best) { best = v[k].y; bidx = e + 1; }
            if (v[k].z > best) { best = v[k].z; bidx = e + 2; }
            if (v[k].w > best) { best = v[k].w; bidx = e + 3; }
        }
    }

    // Warp reduce (tie-break toward smaller index).
    #pragma unroll
    for (int off = 16; off > 0; off >>= 1) {
        float ov = __shfl_down_sync(0xffffffffu, best, off);
        int   oi = __shfl_down_sync(0xffffffffu, bidx, off);
        if (ov > best || (ov == best && oi < bidx)) { best = ov; bidx = oi; }
    }

    __shared__ float sv[THREADS / 32];
    __shared__ int   si[THREADS / 32];
    const int w    = threadIdx.x >> 5;
    const int lane = threadIdx.x & 31;
    if (lane == 0) { sv[w] = best; si[w] = bidx; }
    __syncthreads();

    if (threadIdx.x == 0) {
        float bv = sv[0]; int bi = si[0];
        #pragma unroll
        for (int j = 1; j < THREADS / 32; j++) {
            if (sv[j] > bv || (sv[j] == bv && si[j] < bi)) { bv = sv[j]; bi = si[j]; }
        }
        g_val[cta] = bv;
        g_idx[cta] = bi;
        __threadfence();

        const int b = row >> 3;                       // batch index
        int old = atomicAdd(&g_done[b], 1);
        if (old == 15) {                              // last of 16 half-rows
            g_done[b] = 0;                            // reset for next graph replay
            __threadfence();                          // order reads after the observed adds

            // Combine halves -> per-spec target tokens.
            int tt[NUM_SPEC];
            #pragma unroll
            for (int j = 0; j < NUM_SPEC; j++) {
                int r = b * NUM_SPEC + j;
                float v0 = g_val[2 * r], v1 = g_val[2 * r + 1];
                tt[j] = (v0 >= v1) ? g_idx[2 * r] : g_idx[2 * r + 1];
            }

            // Prefix accept logic.
            int num_accept = 0;
            bool prefix = true;
            #pragma unroll
            for (int j = 0; j < NUM_SPEC; j++) {
                if (prefix) {
                    if (draft[b * NUM_SPEC + j] == tt[j]) num_accept++;
                    else prefix = false;
                }
            }
            const bool all_acc  = (num_accept == NUM_SPEC);
            const int  keep_cnt = all_acc ? NUM_SPEC : (num_accept + 1);
            const int  bon      = bonus[b];

            #pragma unroll
            for (int j = 0; j < NUM_SPEC; j++) {
                out[b * (NUM_SPEC + 1) + j] = (j < keep_cnt) ? (float)tt[j] : -1.0f;
            }
            out[b * (NUM_SPEC + 1) + NUM_SPEC] = all_acc ? (float)bon : -1.0f;
            out[BATCH * (NUM_SPEC + 1) + b]    = (float)(NUM_SPEC - num_accept);
            out[BATCH * (NUM_SPEC + 1) + BATCH + b] =
                all_acc ? (float)bon : (float)tt[num_accept];
        }
    }
}

extern "C" void kernel_launch(void* const* d_in, const int* in_sizes, int n_in,
                              void* d_out, int out_size)
{
    const float* logits = (const float*)d_in[0];
    const int*   draft  = (const int*)d_in[1];
    const int*   bonus  = (const int*)d_in[2];
    float*       out    = (float*)d_out;

    fused_rejection_kernel<<<HALVES, THREADS>>>(logits, draft, bonus, out);
}